// round 16
// baseline (speedup 1.0000x reference)
#include <cuda_runtime.h>
#include <cuda_fp16.h>
#include <cstdint>

// Problem constants
#define BB 32
#define TT 200
#define EE 32
#define HH 128
#define VV 8000
#define MM (BB*TT)   // 6400

// Static scratch: plain fp16 copies. hs is B-MAJOR (row m = b*TT + t).
__device__ alignas(256) __half g_hs[MM * HH];
__device__ alignas(256) __half g_vw[VV * HH];

// ---------------------------------------------------------------------------
// portable PTX helpers (no tcgen05 — compute_103 virtual target)
// ---------------------------------------------------------------------------
__device__ __forceinline__ uint32_t smem_u32(const void* p) {
    uint32_t a;
    asm("{ .reg .u64 t; cvta.to.shared.u64 t, %1; cvt.u32.u64 %0, t; }"
        : "=r"(a) : "l"(p));
    return a;
}
__device__ __forceinline__ void cpasync16(uint32_t dst, const void* src) {
    asm volatile("cp.async.cg.shared.global [%0], [%1], 16;" :: "r"(dst), "l"(src));
}
__device__ __forceinline__ void cpasync_commit() {
    asm volatile("cp.async.commit_group;" ::: "memory");
}
template<int N>
__device__ __forceinline__ void cpasync_wait() {
    asm volatile("cp.async.wait_group %0;" :: "n"(N) : "memory");
}
__device__ __forceinline__ void ldsm4(uint32_t* r, uint32_t addr) {
    asm volatile("ldmatrix.sync.aligned.m8n8.x4.shared.b16 {%0,%1,%2,%3}, [%4];"
                 : "=r"(r[0]), "=r"(r[1]), "=r"(r[2]), "=r"(r[3]) : "r"(addr));
}
__device__ __forceinline__ void mma_f16(float* c, const uint32_t* a,
                                        uint32_t b0, uint32_t b1) {
    asm volatile(
        "mma.sync.aligned.m16n8k16.row.col.f32.f16.f16.f32 "
        "{%0,%1,%2,%3}, {%4,%5,%6,%7}, {%8,%9}, {%0,%1,%2,%3};"
        : "+f"(c[0]), "+f"(c[1]), "+f"(c[2]), "+f"(c[3])
        : "r"(a[0]), "r"(a[1]), "r"(a[2]), "r"(a[3]), "r"(b0), "r"(b1));
}
#define FFMA2(acc, a, b) \
    asm("fma.rn.f32x2 %0, %1, %2, %0;" : "+l"(acc) : "l"(a), "l"(b))
#define UNPACK2(lo, hi, v) \
    asm("mov.b64 {%0, %1}, %2;" : "=f"(lo), "=f"(hi) : "l"(v))

__device__ __forceinline__ float ftanh(float x) {
    float e = __expf(2.f * x);
    return 1.f - __fdividef(2.f, e + 1.f);
}

// ---------------------------------------------------------------------------
// Kernel 1: merged prep.
// CTAs 0..31: fused ux + recurrence (one batch each, 256 thr).
//   Step critical path: barrier -> LDS h -> 32 FFMA2 over 4 rotating accs
//   -> shfl reduce -> tanh -> store. U@x dot for step t+1 computed AFTER the
//   store, BEFORE the barrier (off the critical path; x is static).
// CTAs 32..531: convert Vw -> fp16.
// ---------------------------------------------------------------------------
__global__ __launch_bounds__(256, 1) void prep_kernel(
    const float* __restrict__ x,  const float* __restrict__ Ww,
    const float* __restrict__ Wb, const float* __restrict__ Uw,
    const float* __restrict__ Ub, const float* __restrict__ Vw,
    float* __restrict__ hidden_out) {

    __shared__ alignas(16) float xall[TT * EE];
    __shared__ alignas(16) float hbuf[2][HH];

    if (blockIdx.x >= 32) {
        int base = (blockIdx.x - 32) * 1024 + threadIdx.x;   // float2 index
#pragma unroll
        for (int q = 0; q < 4; q++) {
            int i2 = base + q * 256;
            float2 v = ((const float2*)Vw)[i2];
            ((__half2*)g_vw)[i2] = __floats2half2_rn(v.x, v.y);
        }
        return;
    }

    int b = blockIdx.x;
    int tid = threadIdx.x;
    int wrp = tid >> 5;
    int lane = tid & 31;
    int j = wrp * 16 + (lane & 15);
    int s = lane >> 4;

    // packed weights: 64 floats -> 32 f32x2 (u64)
    unsigned long long w2[32];
    {
        const ulonglong2* wr = (const ulonglong2*)(Ww + j * HH + s * 64);
#pragma unroll
        for (int k = 0; k < 16; k++) {
            ulonglong2 v = wr[k];
            w2[2 * k] = v.x; w2[2 * k + 1] = v.y;
        }
    }
    unsigned long long u2[8];
    {
        const ulonglong2* ur = (const ulonglong2*)(Uw + j * EE + s * 16);
#pragma unroll
        for (int k = 0; k < 4; k++) {
            ulonglong2 v = ur[k];
            u2[2 * k] = v.x; u2[2 * k + 1] = v.y;
        }
    }
    float bj = Ub[j] + Wb[j];

    {
        const float4* xsrc = (const float4*)(x + (size_t)b * TT * EE);
        float4* xdst = (float4*)xall;
        for (int i = tid; i < TT * EE / 4; i += 256) xdst[i] = xsrc[i];
    }
    if (tid < HH) hbuf[0][tid] = 0.f;
    __syncthreads();

    __half* hs = g_hs + (size_t)b * TT * HH;

    // u-dot for t = 0
    float uacc;
    {
        unsigned long long ua = 0ull, ub2 = 0ull;
        const ulonglong2* xt = (const ulonglong2*)(xall + s * 16);
#pragma unroll
        for (int e = 0; e < 4; e++) {
            ulonglong2 x2 = xt[e];
            FFMA2(ua, u2[2 * e], x2.x);
            FFMA2(ub2, u2[2 * e + 1], x2.y);
        }
        float q0, q1, q2, q3;
        UNPACK2(q0, q1, ua);
        UNPACK2(q2, q3, ub2);
        uacc = (q0 + q1) + (q2 + q3);
    }

    int cur = 0;
    float hv = 0.f;
    for (int t = 0; t < TT; t++) {
        // W @ h over 4 rotating packed accumulators (chain depth 8)
        unsigned long long aA = 0ull, aB = 0ull, aC = 0ull, aD = 0ull;
        const ulonglong2* hb = (const ulonglong2*)(hbuf[cur] + s * 64);
#pragma unroll
        for (int k = 0; k < 16; k += 2) {
            ulonglong2 h2a = hb[k];
            ulonglong2 h2b = hb[k + 1];
            FFMA2(aA, w2[2 * k],     h2a.x);
            FFMA2(aB, w2[2 * k + 1], h2a.y);
            FFMA2(aC, w2[2 * k + 2], h2b.x);
            FFMA2(aD, w2[2 * k + 3], h2b.y);
        }
        float p0, p1, p2, p3, p4, p5, p6, p7;
        UNPACK2(p0, p1, aA);
        UNPACK2(p2, p3, aB);
        UNPACK2(p4, p5, aC);
        UNPACK2(p6, p7, aD);
        float acc = ((p0 + p1) + (p2 + p3)) + ((p4 + p5) + (p6 + p7)) + uacc;
        acc += __shfl_xor_sync(0xffffffffu, acc, 16);
        hv = ftanh(acc + bj);
        if (s == 0) {
            hbuf[cur ^ 1][j] = hv;
            hs[t * HH + j] = __float2half_rn(hv);
        }
        // u-dot for t+1 (independent of h) — fills time before the barrier
        if (t + 1 < TT) {
            unsigned long long ua = 0ull, ub2 = 0ull;
            const ulonglong2* xt = (const ulonglong2*)(xall + (t + 1) * EE + s * 16);
#pragma unroll
            for (int e = 0; e < 4; e++) {
                ulonglong2 x2 = xt[e];
                FFMA2(ua, u2[2 * e], x2.x);
                FFMA2(ub2, u2[2 * e + 1], x2.y);
            }
            float q0, q1, q2, q3;
            UNPACK2(q0, q1, ua);
            UNPACK2(q2, q3, ub2);
            uacc = (q0 + q1) + (q2 + q3);
        }
        __syncthreads();
        cur ^= 1;
    }
    if (s == 0) hidden_out[b * HH + j] = hv;
}

// ---------------------------------------------------------------------------
// Kernel 2: plain fp16 HMMA GEMM, tile 128x160, 2 CTAs/SM (smem ~72.6KB).
// C[6400x8000] = hs @ Vw^T + Vb  (fp32 accum).
// K=128 resident. 256 thr = 8 warps (4m x 2n), warp tile 32x80.
// SMEM rows: 256B, 16 chunks of 16B, swizzle chunk c -> c ^ (row & 7).
// hs is B-MAJOR (row m = b*TT + t) -> epilogue writes C rows directly.
// ---------------------------------------------------------------------------
#define SA    0
#define SB    32768
#define SBIAS 73728
#define GEMM_SMEM (73728 + 640)

__global__ __launch_bounds__(256, 2) void gemm_hmma_kernel(
    const float* __restrict__ bias, float* __restrict__ C) {
    extern __shared__ char smem[];
    uint32_t sb = smem_u32(smem);
    int tid = threadIdx.x;
    int wid = tid >> 5;
    int lid = tid & 31;
    int warp_m = wid & 3;        // 32 rows each
    int warp_n = wid >> 2;       // 80 cols each
    int ntile = blockIdx.x * 160;
    int mtile = blockIdx.y * 128;

    float* bias_s = (float*)(smem + SBIAS);
    if (tid < 160) bias_s[tid] = bias[ntile + tid];

    // B tile (160 rows x 16 chunks)
    {
        const uint4* bsrc = (const uint4*)g_vw + (size_t)ntile * 16;
#pragma unroll
        for (int i = tid; i < 2560; i += 256) {
            int row = i >> 4, c = i & 15;
            uint32_t off = (uint32_t)row * 256u + (uint32_t)((c ^ (row & 7)) << 4);
            cpasync16(sb + SB + off, bsrc + i);
        }
    }
    // A tile (128 rows x 16 chunks)
    {
        const uint4* asrc = (const uint4*)g_hs + (size_t)mtile * 16;
#pragma unroll
        for (int i = tid; i < 2048; i += 256) {
            int row = i >> 4, c = i & 15;
            uint32_t off = (uint32_t)row * 256u + (uint32_t)((c ^ (row & 7)) << 4);
            cpasync16(sb + SA + off, asrc + i);
        }
    }
    cpasync_commit();
    cpasync_wait<0>();
    __syncthreads();

    // lane geometry
    int ra = warp_m * 32 + (lid & 15);
    int r7 = ra & 7;
    uint32_t a_row = sb + SA + (uint32_t)ra * 256u;
    int ca = (lid >> 4);

    int nb = warp_n * 80 + (lid & 7) + ((lid >> 4) << 3);
    int n7 = lid & 7;
    int cb = (lid >> 3) & 1;
    uint32_t b_row = sb + SB + (uint32_t)nb * 256u;

    float acc[2][10][4];
#pragma unroll
    for (int im = 0; im < 2; im++)
#pragma unroll
        for (int s = 0; s < 10; s++)
#pragma unroll
            for (int q = 0; q < 4; q++) acc[im][s][q] = 0.f;

#pragma unroll
    for (int k = 0; k < 8; k++) {
        uint32_t offA = (uint32_t)(((k * 2 + ca) ^ r7) << 4);
        uint32_t offB = (uint32_t)(((k * 2 + cb) ^ n7) << 4);
        uint32_t af[8], bf[20];
        ldsm4(af,     a_row + offA);
        ldsm4(af + 4, a_row + 4096 + offA);
#pragma unroll
        for (int jj = 0; jj < 5; jj++)
            ldsm4(bf + jj * 4, b_row + jj * 4096 + offB);
#pragma unroll
        for (int im = 0; im < 2; im++)
#pragma unroll
            for (int s = 0; s < 10; s++) {
                int bi = (s >> 1) * 4 + (s & 1) * 2;
                mma_f16(acc[im][s], af + im * 4, bf[bi], bf[bi + 1]);
            }
    }

    // epilogue: direct row mapping (b-major hs rows == C rows)
    int r0 = mtile + warp_m * 32 + (lid >> 2);
    int cbase = warp_n * 80 + (lid & 3) * 2;
#pragma unroll
    for (int im = 0; im < 2; im++) {
#pragma unroll
        for (int s = 0; s < 10; s++) {
            int col = cbase + s * 8;
            float b0 = bias_s[col], b1 = bias_s[col + 1];
            float* p0 = C + (size_t)(r0 + im * 16) * VV + ntile + col;
            float* p1 = p0 + (size_t)8 * VV;
            *(float2*)p0 = make_float2(acc[im][s][0] + b0, acc[im][s][1] + b1);
            *(float2*)p1 = make_float2(acc[im][s][2] + b0, acc[im][s][3] + b1);
        }
    }
}

// ---------------------------------------------------------------------------
extern "C" void kernel_launch(void* const* d_in, const int* in_sizes, int n_in,
                              void* d_out, int out_size) {
    const float* x  = (const float*)d_in[0];
    const float* Ww = (const float*)d_in[1];
    const float* Wb = (const float*)d_in[2];
    const float* Uw = (const float*)d_in[3];
    const float* Ub = (const float*)d_in[4];
    const float* Vw = (const float*)d_in[5];
    const float* Vb = (const float*)d_in[6];

    float* out    = (float*)d_out;
    float* hidden = out + (size_t)BB * TT * VV;

    cudaFuncSetAttribute(gemm_hmma_kernel,
                         cudaFuncAttributeMaxDynamicSharedMemorySize, GEMM_SMEM);

    prep_kernel<<<532, 256>>>(x, Ww, Wb, Uw, Ub, Vw, hidden);
    dim3 grid(VV / 160, MM / 128);
    gemm_hmma_kernel<<<grid, 256, GEMM_SMEM>>>(Vb, out);
}